// round 2
// baseline (speedup 1.0000x reference)
#include <cuda_runtime.h>
#include <cstdio>

// EmbedSocialFeatures: 3-layer MLP (64->32->64->128, ReLU on first two) + segment mean.
// Layer 3 is linear => commutes with the segment sum: apply W3/b3 once per
// segment to the segment-mean of relu(h2). Cuts FLOPs 3x (24.6G -> 8.3G).
// seg_ids sorted => one CTA per segment via binary search, no atomics.

#define TPB 128
#define ROWS_PER_BATCH 128
#define FS_STRIDE 68  // 64 + 4 pad: (t*68+k)%32 = (4t+k)%32 varies with t -> conflict-free

// dynamic smem layout (floats):
//  W1s[2048] W2s[2048] b1s[32] b2s[64] acc[64] fs[128*68]
#define SMEM_FLOATS (2048 + 2048 + 32 + 64 + 64 + ROWS_PER_BATCH * FS_STRIDE)
#define SMEM_BYTES (SMEM_FLOATS * 4)

__device__ __forceinline__ int lower_bound_dev(const int* __restrict__ a, int n, int v) {
    int lo = 0, hi = n;
    while (lo < hi) {
        int m = (lo + hi) >> 1;
        if (__ldg(a + m) < v) lo = m + 1; else hi = m;
    }
    return lo;
}

extern __shared__ float smem_f[];

__global__ __launch_bounds__(TPB)
void seg_mlp_kernel(const float* __restrict__ f_all,
                    const int*   __restrict__ seg_ids, int N,
                    const float* __restrict__ W1, const float* __restrict__ b1,
                    const float* __restrict__ W2, const float* __restrict__ b2,
                    const float* __restrict__ W3, const float* __restrict__ b3,
                    float* __restrict__ out)
{
    float* W1s = smem_f;            // [64*32] row k -> 32 contiguous outputs
    float* W2s = W1s + 2048;        // [32*64]
    float* b1s = W2s + 2048;        // [32]
    float* b2s = b1s + 32;          // [64]
    float* acc = b2s + 64;          // [64] segment sum of relu(h2)
    float* fs  = acc + 64;          // [128*68] row tile (reused for h1/h2 stash)
    __shared__ int range2[2];

    const int tid = threadIdx.x;
    const int s   = blockIdx.x;

    // stage weights (uniform-broadcast reads later)
    for (int i = tid; i < 2048; i += TPB) W1s[i] = W1[i];
    for (int i = tid; i < 2048; i += TPB) W2s[i] = W2[i];
    if (tid < 32) b1s[tid] = b1[tid];
    if (tid < 64) { b2s[tid] = b2[tid]; acc[tid] = 0.0f; }
    if (tid == 0) {
        range2[0] = lower_bound_dev(seg_ids, N, s);
        range2[1] = lower_bound_dev(seg_ids, N, s + 1);
    }
    __syncthreads();

    const int start = range2[0];
    const int end   = range2[1];
    const int count = end - start;

    for (int base = start; base < end; base += ROWS_PER_BATCH) {
        const int nb = min(ROWS_PER_BATCH, end - base);

        // coalesced float4 tile load: rows [base, base+nb)
        const float4* g4 = reinterpret_cast<const float4*>(f_all + (size_t)base * 64);
        const int tot4 = nb * 16;
        for (int i = tid; i < tot4; i += TPB) {
            const int r = i >> 4, q = i & 15;
            float4 v = g4[i];
            *reinterpret_cast<float4*>(&fs[r * FS_STRIDE + q * 4]) = v;
        }
        __syncthreads();

        if (tid < nb) {
            float* frow = &fs[tid * FS_STRIDE];

            // ---- layer 1: 64 -> 32 ----
            float h1[32];
            #pragma unroll
            for (int j = 0; j < 32; j++) h1[j] = b1s[j];
            #pragma unroll 8
            for (int k = 0; k < 64; k++) {
                const float fk = frow[k];
                #pragma unroll
                for (int j = 0; j < 32; j++)
                    h1[j] = fmaf(fk, W1s[k * 32 + j], h1[j]);
            }
            // relu; stash over the (now dead) f row so layer-2 k stays dynamic-indexable
            #pragma unroll
            for (int j = 0; j < 32; j++) frow[j] = fmaxf(h1[j], 0.0f);

            // ---- layer 2: 32 -> 64 ----
            float h2[64];
            #pragma unroll
            for (int j = 0; j < 64; j++) h2[j] = b2s[j];
            #pragma unroll 4
            for (int k = 0; k < 32; k++) {
                const float a = frow[k];
                #pragma unroll
                for (int j = 0; j < 64; j++)
                    h2[j] = fmaf(a, W2s[k * 64 + j], h2[j]);
            }
            // relu(h2) back into the row for the cross-row reduction
            #pragma unroll
            for (int j = 0; j < 64; j++) frow[j] = fmaxf(h2[j], 0.0f);
        }
        __syncthreads();

        // column reduction: thread c (<64) sums column c over nb rows
        if (tid < 64) {
            float a0 = 0.f, a1 = 0.f, a2 = 0.f, a3 = 0.f;
            int r = 0;
            for (; r + 4 <= nb; r += 4) {
                a0 += fs[(r + 0) * FS_STRIDE + tid];
                a1 += fs[(r + 1) * FS_STRIDE + tid];
                a2 += fs[(r + 2) * FS_STRIDE + tid];
                a3 += fs[(r + 3) * FS_STRIDE + tid];
            }
            for (; r < nb; r++) a0 += fs[r * FS_STRIDE + tid];
            acc[tid] += (a0 + a1) + (a2 + a3);
        }
        __syncthreads();
    }

    // ---- per-segment layer 3: out[s, tid] = mean_h2 @ W3[:, tid] + b3[tid] ----
    float res = 0.0f;
    if (count > 0) {
        const float inv = 1.0f / (float)count;
        float d = 0.0f;
        #pragma unroll 8
        for (int j = 0; j < 64; j++)
            d = fmaf(acc[j] * inv, W3[j * 128 + tid], d);   // W3 coalesced, L2-resident
        res = d + b3[tid];
    }
    out[(size_t)s * 128 + tid] = res;   // empty segment -> exact zeros (ref: sum/max(cnt,1))
}

extern "C" void kernel_launch(void* const* d_in, const int* in_sizes, int n_in,
                              void* d_out, int out_size) {
    // metadata order: f_all, seg_ids, num_segments, W1, b1, W2, b2, W3, b3
    const float* f_all   = (const float*)d_in[0];
    const int*   seg_ids = (const int*)  d_in[1];
    const float* W1      = (const float*)d_in[3];
    const float* b1      = (const float*)d_in[4];
    const float* W2      = (const float*)d_in[5];
    const float* b2      = (const float*)d_in[6];
    const float* W3      = (const float*)d_in[7];
    const float* b3      = (const float*)d_in[8];
    float* out = (float*)d_out;

    const int N = in_sizes[1];          // element count of seg_ids
    const int S = out_size / 128;       // segments

    // >48KB dynamic smem opt-in (attribute set is immediate, not stream-ordered;
    // idempotent per call, safe under graph capture)
    cudaFuncSetAttribute(seg_mlp_kernel,
                         cudaFuncAttributeMaxDynamicSharedMemorySize, SMEM_BYTES);

    seg_mlp_kernel<<<S, TPB, SMEM_BYTES>>>(f_all, seg_ids, N,
                                           W1, b1, W2, b2, W3, b3, out);
}

// round 6
// speedup vs baseline: 1.1631x; 1.1631x over previous
#include <cuda_runtime.h>
#include <cstdio>

// EmbedSocialFeatures: 3-layer MLP (64->32->64->128, ReLU on first two) + segment mean.
// Layer 3 commutes with the segment mean -> applied once per segment (3x FLOP cut).
// R3 (resubmit after infra failure): packed fp32 math via PTX fma.rn.f32x2 (SASS
// FFMA2, 2 FMAs/instr on B300's half-rate fma pipe) + conflict-free fs stride 65
// + LDS.128 weight reads.

#define TPB 128
#define ROWS_PER_BATCH 128
#define FS_STRIDE 65  // (65*t+k)%32 = (t+k)%32 -> scalar frow[k]/column reads conflict-free

// dynamic smem floats: W1s[2048] W2s[2048] b1s[32] b2s[64] acc[64] fs[128*65]
#define SMEM_FLOATS (2048 + 2048 + 32 + 64 + 64 + ROWS_PER_BATCH * FS_STRIDE)
#define SMEM_BYTES (SMEM_FLOATS * 4)

typedef unsigned long long u64;

__device__ __forceinline__ u64 pack_dup(float x) {
    u64 r;
    asm("mov.b64 %0, {%1, %1};" : "=l"(r) : "f"(x));
    return r;
}
__device__ __forceinline__ u64 fma2(u64 a, u64 b, u64 c) {
    u64 r;
    asm("fma.rn.f32x2 %0, %1, %2, %3;" : "=l"(r) : "l"(a), "l"(b), "l"(c));
    return r;
}
__device__ __forceinline__ float2 unpack2(u64 v) {
    float lo, hi;
    asm("mov.b64 {%0, %1}, %2;" : "=f"(lo), "=f"(hi) : "l"(v));
    return make_float2(lo, hi);
}

__device__ __forceinline__ int lower_bound_dev(const int* __restrict__ a, int n, int v) {
    int lo = 0, hi = n;
    while (lo < hi) {
        int m = (lo + hi) >> 1;
        if (__ldg(a + m) < v) lo = m + 1; else hi = m;
    }
    return lo;
}

extern __shared__ float smem_f[];

__global__ __launch_bounds__(TPB)
void seg_mlp_kernel(const float* __restrict__ f_all,
                    const int*   __restrict__ seg_ids, int N,
                    const float* __restrict__ W1, const float* __restrict__ b1,
                    const float* __restrict__ W2, const float* __restrict__ b2,
                    const float* __restrict__ W3, const float* __restrict__ b3,
                    float* __restrict__ out)
{
    float* W1s = smem_f;            // [64*32]
    float* W2s = W1s + 2048;        // [32*64]
    float* b1s = W2s + 2048;        // [32]
    float* b2s = b1s + 32;          // [64]
    float* acc = b2s + 64;          // [64]
    float* fs  = acc + 64;          // [128*65]
    __shared__ int range2[2];

    const int tid = threadIdx.x;
    const int s   = blockIdx.x;

    // stage weights, vectorized
    {
        const float4* w1g = reinterpret_cast<const float4*>(W1);
        const float4* w2g = reinterpret_cast<const float4*>(W2);
        float4* w1s4 = reinterpret_cast<float4*>(W1s);
        float4* w2s4 = reinterpret_cast<float4*>(W2s);
        #pragma unroll
        for (int i = 0; i < 4; i++) w1s4[tid + i * TPB] = w1g[tid + i * TPB];
        #pragma unroll
        for (int i = 0; i < 4; i++) w2s4[tid + i * TPB] = w2g[tid + i * TPB];
    }
    if (tid < 32) b1s[tid] = b1[tid];
    if (tid < 64) { b2s[tid] = b2[tid]; acc[tid] = 0.0f; }
    if (tid == 0) {
        range2[0] = lower_bound_dev(seg_ids, N, s);
        range2[1] = lower_bound_dev(seg_ids, N, s + 1);
    }
    __syncthreads();

    const int start = range2[0];
    const int end   = range2[1];
    const int count = end - start;

    for (int base = start; base < end; base += ROWS_PER_BATCH) {
        const int nb = min(ROWS_PER_BATCH, end - base);

        // coalesced float4 global read; scalar smem stores (stride-65 layout)
        const float4* g4 = reinterpret_cast<const float4*>(f_all + (size_t)base * 64);
        const int tot4 = nb * 16;
        for (int i = tid; i < tot4; i += TPB) {
            const int r = i >> 4, q = i & 15;
            float4 v = g4[i];
            float* p = &fs[r * FS_STRIDE + q * 4];
            p[0] = v.x; p[1] = v.y; p[2] = v.z; p[3] = v.w;
        }
        __syncthreads();

        if (tid < nb) {
            float* frow = &fs[tid * FS_STRIDE];

            // ---- layer 1: 64 -> 32, packed f32x2 (16 accumulators) ----
            u64 h1[16];
            {
                const u64* b1p = reinterpret_cast<const u64*>(b1s);
                #pragma unroll
                for (int j = 0; j < 16; j++) h1[j] = b1p[j];
            }
            #pragma unroll 8
            for (int k = 0; k < 64; k++) {
                const u64 fk = pack_dup(frow[k]);                 // conflict-free LDS
                const ulonglong2* wrow =
                    reinterpret_cast<const ulonglong2*>(&W1s[k * 32]);
                #pragma unroll
                for (int j = 0; j < 8; j++) {                     // 8x LDS.128 broadcast
                    ulonglong2 w = wrow[j];
                    h1[2 * j]     = fma2(fk, w.x, h1[2 * j]);
                    h1[2 * j + 1] = fma2(fk, w.y, h1[2 * j + 1]);
                }
            }
            // relu -> stash over dead f row (keeps layer-2 k dynamically indexable)
            #pragma unroll
            for (int j = 0; j < 16; j++) {
                float2 v = unpack2(h1[j]);
                frow[2 * j]     = fmaxf(v.x, 0.0f);
                frow[2 * j + 1] = fmaxf(v.y, 0.0f);
            }

            // ---- layer 2: 32 -> 64, packed f32x2 (32 accumulators) ----
            u64 h2[32];
            {
                const u64* b2p = reinterpret_cast<const u64*>(b2s);
                #pragma unroll
                for (int j = 0; j < 32; j++) h2[j] = b2p[j];
            }
            #pragma unroll 4
            for (int k = 0; k < 32; k++) {
                const u64 a = pack_dup(frow[k]);
                const ulonglong2* wrow =
                    reinterpret_cast<const ulonglong2*>(&W2s[k * 64]);
                #pragma unroll
                for (int j = 0; j < 16; j++) {                    // 16x LDS.128 broadcast
                    ulonglong2 w = wrow[j];
                    h2[2 * j]     = fma2(a, w.x, h2[2 * j]);
                    h2[2 * j + 1] = fma2(a, w.y, h2[2 * j + 1]);
                }
            }
            // relu(h2) back to the row for the cross-row reduction
            #pragma unroll
            for (int j = 0; j < 32; j++) {
                float2 v = unpack2(h2[j]);
                frow[2 * j]     = fmaxf(v.x, 0.0f);
                frow[2 * j + 1] = fmaxf(v.y, 0.0f);
            }
        }
        __syncthreads();

        // column reduction: thread c (<64) sums column c over nb rows (conflict-free)
        if (tid < 64) {
            float a0 = 0.f, a1 = 0.f, a2 = 0.f, a3 = 0.f;
            int r = 0;
            for (; r + 4 <= nb; r += 4) {
                a0 += fs[(r + 0) * FS_STRIDE + tid];
                a1 += fs[(r + 1) * FS_STRIDE + tid];
                a2 += fs[(r + 2) * FS_STRIDE + tid];
                a3 += fs[(r + 3) * FS_STRIDE + tid];
            }
            for (; r < nb; r++) a0 += fs[r * FS_STRIDE + tid];
            acc[tid] += (a0 + a1) + (a2 + a3);
        }
        __syncthreads();
    }

    // ---- per-segment layer 3: out[s, tid] = mean_h2 @ W3[:, tid] + b3[tid] ----
    float res = 0.0f;
    if (count > 0) {
        const float inv = 1.0f / (float)count;
        float d = 0.0f;
        #pragma unroll 8
        for (int j = 0; j < 64; j++)
            d = fmaf(acc[j] * inv, W3[j * 128 + tid], d);   // coalesced, L2-resident
        res = d + b3[tid];
    }
    out[(size_t)s * 128 + tid] = res;   // empty segment -> exact zeros

}

extern "C" void kernel_launch(void* const* d_in, const int* in_sizes, int n_in,
                              void* d_out, int out_size) {
    // metadata order: f_all, seg_ids, num_segments, W1, b1, W2, b2, W3, b3
    const float* f_all   = (const float*)d_in[0];
    const int*   seg_ids = (const int*)  d_in[1];
    const float* W1      = (const float*)d_in[3];
    const float* b1      = (const float*)d_in[4];
    const float* W2      = (const float*)d_in[5];
    const float* b2      = (const float*)d_in[6];
    const float* W3      = (const float*)d_in[7];
    const float* b3      = (const float*)d_in[8];
    float* out = (float*)d_out;

    const int N = in_sizes[1];
    const int S = out_size / 128;

    cudaFuncSetAttribute(seg_mlp_kernel,
                         cudaFuncAttributeMaxDynamicSharedMemorySize, SMEM_BYTES);

    seg_mlp_kernel<<<S, TPB, SMEM_BYTES>>>(f_all, seg_ids, N,
                                           W1, b1, W2, b2, W3, b3, out);
}

// round 9
// speedup vs baseline: 1.6557x; 1.4236x over previous
#include <cuda_runtime.h>
#include <cstdint>

// EmbedSocialFeatures: 3-layer MLP (64->32->64->128, ReLU x2) + segment mean.
// Layer 3 commutes with the mean -> per-segment. Layers 1+2 on the tensor pipe
// via arch-portable mma.sync m16n8k8 tf32 (tcgen05 is blocked: harness PTX
// targets sm_103 without the 'a' feature suffix).
// Weights live in smem PRE-ARRANGED in fragment order (1 conflict-free LDS.64
// per fragment). Epilogue reduces relu(h2) in registers via shfl-xor.

#define TPB 128
#define S_TILE 68            // floats/row: STS.128 staging AND frag reads conflict-free
#define TILE_OFF 0           // 128*68*4 = 34816 B (A tile; h1 overlays it per-row)
#define W1F_OFF 34816        // 32 frags * 256 B
#define W2F_OFF 43008        // 32 frags * 256 B
#define B1S_OFF 51200
#define B2S_OFF 51328
#define ACC_OFF 51584        // 64 f32, shared atomicAdd target
#define RNG_OFF 51840
#define SMEM_BYTES 51968     // 4 CTAs/SM fit in 228KB carveout

static __device__ __forceinline__ uint32_t rna_tf32(float x) {
    uint32_t r;
    asm("cvt.rna.tf32.f32 %0, %1;" : "=r"(r) : "f"(x));
    return r;
}

static __device__ __forceinline__ void mma8(float d[4],
                                            uint32_t a0, uint32_t a1, uint32_t a2, uint32_t a3,
                                            uint32_t b0, uint32_t b1) {
    asm volatile(
        "mma.sync.aligned.m16n8k8.row.col.f32.tf32.tf32.f32 "
        "{%0,%1,%2,%3}, {%4,%5,%6,%7}, {%8,%9}, {%0,%1,%2,%3};"
        : "+f"(d[0]), "+f"(d[1]), "+f"(d[2]), "+f"(d[3])
        : "r"(a0), "r"(a1), "r"(a2), "r"(a3), "r"(b0), "r"(b1));
}

static __device__ __forceinline__ int lower_bound_dev(const int* __restrict__ a, int n, int v) {
    int lo = 0, hi = n;
    while (lo < hi) { int m = (lo + hi) >> 1; if (__ldg(a + m) < v) lo = m + 1; else hi = m; }
    return lo;
}

extern __shared__ char smem[];

__global__ __launch_bounds__(TPB, 4)
void seg_mlp_mma_kernel(const float* __restrict__ f_all,
                        const int*   __restrict__ seg_ids, int N,
                        const float* __restrict__ W1, const float* __restrict__ b1,
                        const float* __restrict__ W2, const float* __restrict__ b2,
                        const float* __restrict__ W3, const float* __restrict__ b3,
                        float* __restrict__ out)
{
    const int tid   = threadIdx.x;
    const int lane  = tid & 31;
    const int wbase = (tid >> 5) * 32;      // warp's first row in tile
    const int g     = lane >> 2;            // row group 0..7
    const int tig   = lane & 3;             // thread-in-group 0..3
    const int s     = blockIdx.x;

    uint32_t* tu  = (uint32_t*)(smem + TILE_OFF);   // tile (tf32 bits)
    float*    b1s = (float*)(smem + B1S_OFF);
    float*    b2s = (float*)(smem + B2S_OFF);
    float*    acc = (float*)(smem + ACC_OFF);
    int*      rng = (int*)  (smem + RNG_OFF);

    // ---- W1 fragments: frag f=k*4+n, lane l -> {W1[8k+t][8n+g], W1[8k+t+4][8n+g]} ----
    for (int idx = tid; idx < 1024; idx += TPB) {
        const int f = idx >> 5, l = idx & 31;
        const int k = f >> 2, n = f & 3, gg = l >> 2, t = l & 3;
        uint2 v;
        v.x = rna_tf32(__ldg(&W1[(8 * k + t) * 32 + 8 * n + gg]));
        v.y = rna_tf32(__ldg(&W1[(8 * k + t + 4) * 32 + 8 * n + gg]));
        *(uint2*)(smem + W1F_OFF + f * 256 + l * 8) = v;
    }
    // ---- W2 fragments: frag f = h*16 + k*4 + n, col = 32h+8n+g ----
    for (int idx = tid; idx < 1024; idx += TPB) {
        const int f = idx >> 5, l = idx & 31;
        const int h = f >> 4, k = (f >> 2) & 3, n = f & 3, gg = l >> 2, t = l & 3;
        const int col = 32 * h + 8 * n + gg;
        uint2 v;
        v.x = rna_tf32(__ldg(&W2[(8 * k + t) * 64 + col]));
        v.y = rna_tf32(__ldg(&W2[(8 * k + t + 4) * 64 + col]));
        *(uint2*)(smem + W2F_OFF + f * 256 + l * 8) = v;
    }
    if (tid < 32) b1s[tid] = b1[tid];
    if (tid < 64) { b2s[tid] = b2[tid]; acc[tid] = 0.0f; }
    if (tid == 0) {
        rng[0] = lower_bound_dev(seg_ids, N, s);
        rng[1] = lower_bound_dev(seg_ids, N, s + 1);
    }
    __syncthreads();

    // per-lane bias values for epilogue columns
    float b1v0[4], b1v1[4];
    #pragma unroll
    for (int n = 0; n < 4; n++) { b1v0[n] = b1s[8 * n + 2 * tig]; b1v1[n] = b1s[8 * n + 2 * tig + 1]; }

    const int start = rng[0], end = rng[1], count = end - start;

    for (int base = start; base < end; base += 128) {
        const int nb = min(128, end - base);

        // ---- stage tile: coalesced float4 loads, tf32 convert, stride-68 rows ----
        const float4* g4 = reinterpret_cast<const float4*>(f_all + (size_t)base * 64);
        for (int i = tid; i < nb * 16; i += TPB) {
            const int r = i >> 4, q = i & 15;
            float4 v = g4[i];
            uint4 u;
            u.x = rna_tf32(v.x); u.y = rna_tf32(v.y);
            u.z = rna_tf32(v.z); u.w = rna_tf32(v.w);
            *(uint4*)(&tu[r * S_TILE + 4 * q]) = u;
        }
        // zero-fill tail rows (avoid NaN bit patterns reaching mma)
        for (int i = nb * 16 + tid; i < 2048; i += TPB) {
            const int r = i >> 4, q = i & 15;
            *(uint4*)(&tu[r * S_TILE + 4 * q]) = make_uint4(0, 0, 0, 0);
        }
        __syncthreads();

        if (wbase < nb) {
            // row masks for this warp's 4 row-subtiles
            float fm[2][2];
            #pragma unroll
            for (int m = 0; m < 2; m++) {
                fm[m][0] = (wbase + 16 * m + g      < nb) ? 1.0f : 0.0f;
                fm[m][1] = (wbase + 16 * m + g + 8  < nb) ? 1.0f : 0.0f;
            }

            // ---- layer 1: D1[32x32] = A[32x64] @ W1 ----
            float d1[2][4][4];
            #pragma unroll
            for (int m = 0; m < 2; m++)
                #pragma unroll
                for (int n = 0; n < 4; n++)
                    #pragma unroll
                    for (int c = 0; c < 4; c++) d1[m][n][c] = 0.0f;

            #pragma unroll
            for (int k = 0; k < 8; k++) {
                uint32_t a[2][4];
                #pragma unroll
                for (int m = 0; m < 2; m++) {
                    const int r0 = wbase + 16 * m + g;
                    a[m][0] = tu[r0 * S_TILE + 8 * k + tig];
                    a[m][1] = tu[(r0 + 8) * S_TILE + 8 * k + tig];
                    a[m][2] = tu[r0 * S_TILE + 8 * k + tig + 4];
                    a[m][3] = tu[(r0 + 8) * S_TILE + 8 * k + tig + 4];
                }
                #pragma unroll
                for (int n = 0; n < 4; n++) {
                    uint2 bf = *(const uint2*)(smem + W1F_OFF + (k * 4 + n) * 256 + lane * 8);
                    #pragma unroll
                    for (int m = 0; m < 2; m++)
                        mma8(d1[m][n], a[m][0], a[m][1], a[m][2], a[m][3], bf.x, bf.y);
                }
            }

            // ---- epilogue 1: h1 = tf32(relu(d1 + b1)) overlaid on own tile rows ----
            #pragma unroll
            for (int m = 0; m < 2; m++) {
                const int r0 = wbase + 16 * m + g;
                #pragma unroll
                for (int n = 0; n < 4; n++) {
                    uint2 u0, u1;
                    u0.x = rna_tf32(fmaxf(d1[m][n][0] + b1v0[n], 0.0f));
                    u0.y = rna_tf32(fmaxf(d1[m][n][1] + b1v1[n], 0.0f));
                    u1.x = rna_tf32(fmaxf(d1[m][n][2] + b1v0[n], 0.0f));
                    u1.y = rna_tf32(fmaxf(d1[m][n][3] + b1v1[n], 0.0f));
                    *(uint2*)(&tu[r0 * S_TILE + 8 * n + 2 * tig]) = u0;
                    *(uint2*)(&tu[(r0 + 8) * S_TILE + 8 * n + 2 * tig]) = u1;
                }
            }
            __syncwarp();   // cross-lane h1 visibility within warp

            // ---- layer 2 in two n-halves of 32 cols each ----
            #pragma unroll
            for (int h = 0; h < 2; h++) {
                float bv0[4], bv1[4];
                #pragma unroll
                for (int n = 0; n < 4; n++) {
                    bv0[n] = b2s[32 * h + 8 * n + 2 * tig];
                    bv1[n] = b2s[32 * h + 8 * n + 2 * tig + 1];
                }
                float d2[2][4][4];
                #pragma unroll
                for (int m = 0; m < 2; m++)
                    #pragma unroll
                    for (int n = 0; n < 4; n++)
                        #pragma unroll
                        for (int c = 0; c < 4; c++) d2[m][n][c] = 0.0f;

                #pragma unroll
                for (int k = 0; k < 4; k++) {
                    uint32_t a[2][4];
                    #pragma unroll
                    for (int m = 0; m < 2; m++) {
                        const int r0 = wbase + 16 * m + g;
                        a[m][0] = tu[r0 * S_TILE + 8 * k + tig];
                        a[m][1] = tu[(r0 + 8) * S_TILE + 8 * k + tig];
                        a[m][2] = tu[r0 * S_TILE + 8 * k + tig + 4];
                        a[m][3] = tu[(r0 + 8) * S_TILE + 8 * k + tig + 4];
                    }
                    #pragma unroll
                    for (int n = 0; n < 4; n++) {
                        uint2 bf = *(const uint2*)(smem + W2F_OFF +
                                                   ((h * 4 + k) * 4 + n) * 256 + lane * 8);
                        #pragma unroll
                        for (int m = 0; m < 2; m++)
                            mma8(d2[m][n], a[m][0], a[m][1], a[m][2], a[m][3], bf.x, bf.y);
                    }
                }

                // ---- epilogue 2: masked relu + in-register column reduction ----
                float s0[4], s1[4];
                #pragma unroll
                for (int n = 0; n < 4; n++) {
                    s0[n] = fm[0][0] * fmaxf(d2[0][n][0] + bv0[n], 0.0f)
                          + fm[0][1] * fmaxf(d2[0][n][2] + bv0[n], 0.0f)
                          + fm[1][0] * fmaxf(d2[1][n][0] + bv0[n], 0.0f)
                          + fm[1][1] * fmaxf(d2[1][n][2] + bv0[n], 0.0f);
                    s1[n] = fm[0][0] * fmaxf(d2[0][n][1] + bv1[n], 0.0f)
                          + fm[0][1] * fmaxf(d2[0][n][3] + bv1[n], 0.0f)
                          + fm[1][0] * fmaxf(d2[1][n][1] + bv1[n], 0.0f)
                          + fm[1][1] * fmaxf(d2[1][n][3] + bv1[n], 0.0f);
                }
                #pragma unroll
                for (int mask = 4; mask <= 16; mask <<= 1) {
                    #pragma unroll
                    for (int n = 0; n < 4; n++) {
                        s0[n] += __shfl_xor_sync(0xffffffffu, s0[n], mask);
                        s1[n] += __shfl_xor_sync(0xffffffffu, s1[n], mask);
                    }
                }
                if (g == 0) {
                    #pragma unroll
                    for (int n = 0; n < 4; n++) {
                        atomicAdd(&acc[32 * h + 8 * n + 2 * tig],     s0[n]);
                        atomicAdd(&acc[32 * h + 8 * n + 2 * tig + 1], s1[n]);
                    }
                }
            }
        }
        __syncthreads();
    }

    // ---- per-segment layer 3: out[s][tid] = (acc/count) @ W3[:,tid] + b3[tid] ----
    float res = 0.0f;
    if (count > 0) {
        const float inv = 1.0f / (float)count;
        float d = 0.0f;
        #pragma unroll 8
        for (int j = 0; j < 64; j++)
            d = fmaf(acc[j] * inv, __ldg(&W3[j * 128 + tid]), d);
        res = d + b3[tid];
    }
    out[(size_t)s * 128 + tid] = res;   // empty segment -> exact zeros
}

extern "C" void kernel_launch(void* const* d_in, const int* in_sizes, int n_in,
                              void* d_out, int out_size) {
    // metadata order: f_all, seg_ids, num_segments, W1, b1, W2, b2, W3, b3
    const float* f_all   = (const float*)d_in[0];
    const int*   seg_ids = (const int*)  d_in[1];
    const float* W1      = (const float*)d_in[3];
    const float* b1      = (const float*)d_in[4];
    const float* W2      = (const float*)d_in[5];
    const float* b2      = (const float*)d_in[6];
    const float* W3      = (const float*)d_in[7];
    const float* b3      = (const float*)d_in[8];
    float* out = (float*)d_out;

    const int N = in_sizes[1];
    const int S = out_size / 128;

    cudaFuncSetAttribute(seg_mlp_mma_kernel,
                         cudaFuncAttributeMaxDynamicSharedMemorySize, SMEM_BYTES);

    seg_mlp_mma_kernel<<<S, TPB, SMEM_BYTES>>>(f_all, seg_ids, N,
                                               W1, b1, W2, b2, W3, b3, out);
}

// round 10
// speedup vs baseline: 3.2920x; 1.9882x over previous
#include <cuda_runtime.h>
#include <cstdint>

// EmbedSocialFeatures: 3-layer MLP (64->32->64->128, ReLU x2) + segment mean.
// R10 restructure: (1) zero scratch, (2) persistent tile GEMM over ALL rows with
// cp.async double buffering + mma.sync tf32, segmented-run atomics to global
// scratch, (3) per-segment W3 epilogue. Removes per-segment CTA structure:
// weights staged 296x not 8192x, DRAM latency hidden by prefetch, no partial-
// segment underutilization.

#define TPB_A  256
#define GRID_A 296
#define S_TILE 68      // floats per tile row (STS.128 staging + frag reads conflict-free)
#define ROW_B  272     // bytes per tile row

// ---- smem layout (bytes), kernel A ----
#define TU0_OFF  0          // 34816: tile buffer 0 (128 x 68 f32)
#define TU1_OFF  34816      // 34816: tile buffer 1
#define SEG0_OFF 69632      // 512: seg_ids buffer 0
#define SEG1_OFF 70144      // 512: seg_ids buffer 1
#define W1F_OFF  70656      // 8192: 32 B-frags x 256B
#define W2F_OFF  78848      // 8192: 32 B-frags x 256B
#define B1S_OFF  87040      // 128
#define B2S_OFF  87168      // 256
#define SMEM_A   87424      // 2 CTAs/SM -> 174848 <= 228KB carveout

#define MAXSEG 8192
__device__ float g_acc[MAXSEG * 64];
__device__ float g_cnt[MAXSEG];

static __device__ __forceinline__ uint32_t rna_tf32(float x) {
    uint32_t r;
    asm("cvt.rna.tf32.f32 %0, %1;" : "=r"(r) : "f"(x));
    return r;
}
static __device__ __forceinline__ uint32_t smem_u32(const void* p) {
    uint32_t a;
    asm("{ .reg .u64 t; cvta.to.shared.u64 t, %1; cvt.u32.u64 %0, t; }" : "=r"(a) : "l"(p));
    return a;
}
static __device__ __forceinline__ void mma8(float d[4],
                                            uint32_t a0, uint32_t a1, uint32_t a2, uint32_t a3,
                                            uint32_t b0, uint32_t b1) {
    asm volatile(
        "mma.sync.aligned.m16n8k8.row.col.f32.tf32.tf32.f32 "
        "{%0,%1,%2,%3}, {%4,%5,%6,%7}, {%8,%9}, {%0,%1,%2,%3};"
        : "+f"(d[0]), "+f"(d[1]), "+f"(d[2]), "+f"(d[3])
        : "r"(a0), "r"(a1), "r"(a2), "r"(a3), "r"(b0), "r"(b1));
}
#define CP_ASYNC16(dst, src) \
    asm volatile("cp.async.cg.shared.global [%0], [%1], 16;" :: "r"(dst), "l"(src) : "memory")
#define CP_COMMIT()  asm volatile("cp.async.commit_group;" ::: "memory")
#define CP_WAIT1()   asm volatile("cp.async.wait_group 1;" ::: "memory")

// ---------------- kernel 0: zero scratch ----------------
__global__ void zero_kernel(int S) {
    const int i = blockIdx.x * blockDim.x + threadIdx.x;
    if (i < S * 64) g_acc[i] = 0.0f;
    if (i < S) g_cnt[i] = 0.0f;
}

// ---------------- kernel A: persistent tile GEMM + segmented accumulate ----------------
extern __shared__ char smemA[];

static __device__ __forceinline__ void issue_tile(
    const float* __restrict__ f_all, const int* __restrict__ seg_ids, int Nrows,
    int t, int tid, uint32_t sb_tu, float* tuf, int* segs)
{
    const int base = t * 128;
    const int nb = min(128, Nrows - base);
    const char* src = (const char*)f_all + (size_t)base * 256;
    if (nb == 128) {
        #pragma unroll
        for (int j = 0; j < 8; j++) {
            const int i = tid + j * TPB_A;
            const int r = i >> 4, q = i & 15;
            CP_ASYNC16(sb_tu + (uint32_t)(r * ROW_B + q * 16), src + (size_t)i * 16);
        }
        if (tid < 32)
            CP_ASYNC16(smem_u32(segs) + (uint32_t)(tid * 16),
                       (const char*)(seg_ids + base) + tid * 16);
    } else {
        for (int i = tid; i < nb * 16; i += TPB_A) {
            const int r = i >> 4, q = i & 15;
            CP_ASYNC16(sb_tu + (uint32_t)(r * ROW_B + q * 16), src + (size_t)i * 16);
        }
        // zero pad rows (disjoint addresses from the cp.async region -> no race)
        for (int i = nb * 16 + tid; i < 2048; i += TPB_A) {
            const int r = i >> 4, q = i & 15;
            *(float4*)(&tuf[r * S_TILE + q * 4]) = make_float4(0.f, 0.f, 0.f, 0.f);
        }
        for (int r = tid; r < 128; r += TPB_A)
            segs[r] = __ldg(&seg_ids[base + min(r, nb - 1)]);
    }
}

__global__ __launch_bounds__(TPB_A, 2)
void mlp_accum_kernel(const float* __restrict__ f_all,
                      const int*   __restrict__ seg_ids, int Nrows,
                      const float* __restrict__ W1, const float* __restrict__ b1,
                      const float* __restrict__ W2, const float* __restrict__ b2)
{
    const int tid   = threadIdx.x;
    const int lane  = tid & 31;
    const int wbase = (tid >> 5) * 16;     // warp's 16 rows in tile
    const int g     = lane >> 2;
    const int tig   = lane & 3;

    float* tuf0 = (float*)(smemA + TU0_OFF);
    float* tuf1 = (float*)(smemA + TU1_OFF);
    int*   seg0 = (int*)(smemA + SEG0_OFF);
    int*   seg1 = (int*)(smemA + SEG1_OFF);
    float* b1s  = (float*)(smemA + B1S_OFF);
    float* b2s  = (float*)(smemA + B2S_OFF);
    const uint32_t sb_tu0 = smem_u32(tuf0);
    const uint32_t sb_tu1 = smem_u32(tuf1);

    const int T      = (Nrows + 127) >> 7;
    const int stride = gridDim.x;
    const int t0     = blockIdx.x;

    // prologue: start first tile fetch immediately
    if (t0 < T) issue_tile(f_all, seg_ids, Nrows, t0, tid, sb_tu0, tuf0, seg0);
    CP_COMMIT();

    // ---- stage weight fragments (once per CTA) ----
    // W1 frag f=k*4+n, lane l -> {W1[8k+t][8n+g], W1[8k+t+4][8n+g]}
    for (int idx = tid; idx < 1024; idx += TPB_A) {
        const int f = idx >> 5, l = idx & 31;
        const int k = f >> 2, n = f & 3, gg = l >> 2, t = l & 3;
        uint2 v;
        v.x = rna_tf32(__ldg(&W1[(8 * k + t) * 32 + 8 * n + gg]));
        v.y = rna_tf32(__ldg(&W1[(8 * k + t + 4) * 32 + 8 * n + gg]));
        *(uint2*)(smemA + W1F_OFF + f * 256 + l * 8) = v;
    }
    // W2 frag f = h*16 + k*4 + n, col = 32h+8n+g
    for (int idx = tid; idx < 1024; idx += TPB_A) {
        const int f = idx >> 5, l = idx & 31;
        const int h = f >> 4, k = (f >> 2) & 3, n = f & 3, gg = l >> 2, t = l & 3;
        uint2 v;
        v.x = rna_tf32(__ldg(&W2[(8 * k + t) * 64 + 32 * h + 8 * n + gg]));
        v.y = rna_tf32(__ldg(&W2[(8 * k + t + 4) * 64 + 32 * h + 8 * n + gg]));
        *(uint2*)(smemA + W2F_OFF + f * 256 + l * 8) = v;
    }
    if (tid < 32) b1s[tid] = b1[tid];
    if (tid < 64) b2s[tid] = b2[tid];
    __syncthreads();

    float b1v0[4], b1v1[4];
    #pragma unroll
    for (int n = 0; n < 4; n++) {
        b1v0[n] = b1s[8 * n + 2 * tig];
        b1v1[n] = b1s[8 * n + 2 * tig + 1];
    }

    int buf = 0;
    for (int t = t0; t < T; t += stride) {
        const int nt = t + stride;
        if (nt < T)
            issue_tile(f_all, seg_ids, Nrows, nt, tid,
                       buf ? sb_tu0 : sb_tu1, buf ? tuf0 : tuf1, buf ? seg0 : seg1);
        CP_COMMIT();
        CP_WAIT1();              // current tile's group complete
        __syncthreads();

        float*    tuf  = buf ? tuf1 : tuf0;
        uint32_t* tu   = (uint32_t*)tuf;
        int*      segs = buf ? seg1 : seg0;
        const int nb   = min(128, Nrows - t * 128);
        const int r0   = wbase + g;

        // ---- layer 1: D1[16x32] ----
        float d1[4][4];
        #pragma unroll
        for (int n = 0; n < 4; n++)
            #pragma unroll
            for (int c = 0; c < 4; c++) d1[n][c] = 0.0f;
        #pragma unroll
        for (int k = 0; k < 8; k++) {
            const uint32_t a0 = rna_tf32(tuf[r0 * S_TILE + 8 * k + tig]);
            const uint32_t a1 = rna_tf32(tuf[(r0 + 8) * S_TILE + 8 * k + tig]);
            const uint32_t a2 = rna_tf32(tuf[r0 * S_TILE + 8 * k + tig + 4]);
            const uint32_t a3 = rna_tf32(tuf[(r0 + 8) * S_TILE + 8 * k + tig + 4]);
            #pragma unroll
            for (int n = 0; n < 4; n++) {
                const uint2 bf = *(const uint2*)(smemA + W1F_OFF + (k * 4 + n) * 256 + lane * 8);
                mma8(d1[n], a0, a1, a2, a3, bf.x, bf.y);
            }
        }

        // ---- epilogue 1: h1 = tf32(relu(d1+b1)) overlaid on own rows, cols 0..31 ----
        #pragma unroll
        for (int n = 0; n < 4; n++) {
            uint2 u0, u1;
            u0.x = rna_tf32(fmaxf(d1[n][0] + b1v0[n], 0.0f));
            u0.y = rna_tf32(fmaxf(d1[n][1] + b1v1[n], 0.0f));
            u1.x = rna_tf32(fmaxf(d1[n][2] + b1v0[n], 0.0f));
            u1.y = rna_tf32(fmaxf(d1[n][3] + b1v1[n], 0.0f));
            *(uint2*)(&tu[r0 * S_TILE + 8 * n + 2 * tig]) = u0;
            *(uint2*)(&tu[(r0 + 8) * S_TILE + 8 * n + 2 * tig]) = u1;
        }
        __syncwarp();

        // ---- layer 2: D2[16x64], both 32-col halves before any stash ----
        float d2[2][4][4];
        #pragma unroll
        for (int h = 0; h < 2; h++)
            #pragma unroll
            for (int n = 0; n < 4; n++)
                #pragma unroll
                for (int c = 0; c < 4; c++) d2[h][n][c] = 0.0f;
        #pragma unroll
        for (int k = 0; k < 4; k++) {
            const uint32_t a0 = rna_tf32(tuf[r0 * S_TILE + 8 * k + tig]);
            const uint32_t a1 = rna_tf32(tuf[(r0 + 8) * S_TILE + 8 * k + tig]);
            const uint32_t a2 = rna_tf32(tuf[r0 * S_TILE + 8 * k + tig + 4]);
            const uint32_t a3 = rna_tf32(tuf[(r0 + 8) * S_TILE + 8 * k + tig + 4]);
            #pragma unroll
            for (int h = 0; h < 2; h++)
                #pragma unroll
                for (int n = 0; n < 4; n++) {
                    const uint2 bf = *(const uint2*)(smemA + W2F_OFF +
                                                     ((h * 4 + k) * 4 + n) * 256 + lane * 8);
                    mma8(d2[h][n], a0, a1, a2, a3, bf.x, bf.y);
                }
        }

        // ---- epilogue 2: masked relu(h2) stashed over own rows (cols 0..63) ----
        {
            const float m0 = (r0 < nb) ? 1.0f : 0.0f;
            const float m1 = (r0 + 8 < nb) ? 1.0f : 0.0f;
            #pragma unroll
            for (int h = 0; h < 2; h++)
                #pragma unroll
                for (int n = 0; n < 4; n++) {
                    const int c = 32 * h + 8 * n + 2 * tig;
                    const float bv0 = b2s[c], bv1 = b2s[c + 1];
                    float2 v0, v1;
                    v0.x = m0 * fmaxf(d2[h][n][0] + bv0, 0.0f);
                    v0.y = m0 * fmaxf(d2[h][n][1] + bv1, 0.0f);
                    v1.x = m1 * fmaxf(d2[h][n][2] + bv0, 0.0f);
                    v1.y = m1 * fmaxf(d2[h][n][3] + bv1, 0.0f);
                    *(float2*)(&tuf[r0 * S_TILE + c]) = v0;
                    *(float2*)(&tuf[(r0 + 8) * S_TILE + c]) = v1;
                }
        }
        __syncthreads();

        // ---- segmented run-scan: quarter q rows [32q,32q+32), column c ----
        {
            const int q = tid >> 6, c = tid & 63;
            const int rq = q * 32;
            int cur = segs[rq];
            float run = 0.0f, crun = 0.0f;
            #pragma unroll 4
            for (int r = rq; r < rq + 32; r++) {
                const int sg = segs[r];
                if (sg != cur) {
                    atomicAdd(&g_acc[cur * 64 + c], run);
                    if (c == 0) atomicAdd(&g_cnt[cur], crun);
                    run = 0.0f; crun = 0.0f; cur = sg;
                }
                run += tuf[r * S_TILE + c];
                if (r < nb) crun += 1.0f;
            }
            atomicAdd(&g_acc[cur * 64 + c], run);
            if (c == 0) atomicAdd(&g_cnt[cur], crun);
        }
        __syncthreads();
        buf ^= 1;
    }
}

// ---------------- kernel B: per-segment mean @ W3 + b3 ----------------
__global__ __launch_bounds__(128)
void seg_out_kernel(const float* __restrict__ W3, const float* __restrict__ b3,
                    float* __restrict__ out)
{
    const int s = blockIdx.x, tid = threadIdx.x;
    __shared__ float m[64];
    __shared__ float invc;
    if (tid == 0) {
        const float c = g_cnt[s];
        invc = (c > 0.0f) ? (1.0f / c) : 0.0f;
    }
    if (tid < 64) m[tid] = g_acc[s * 64 + tid];
    __syncthreads();
    float res = 0.0f;
    const float inv = invc;
    if (inv > 0.0f) {
        float d = 0.0f;
        #pragma unroll 8
        for (int j = 0; j < 64; j++)
            d = fmaf(m[j] * inv, __ldg(&W3[j * 128 + tid]), d);
        res = d + b3[tid];
    }
    out[(size_t)s * 128 + tid] = res;   // empty segment -> exact zeros
}

extern "C" void kernel_launch(void* const* d_in, const int* in_sizes, int n_in,
                              void* d_out, int out_size) {
    // metadata order: f_all, seg_ids, num_segments, W1, b1, W2, b2, W3, b3
    const float* f_all   = (const float*)d_in[0];
    const int*   seg_ids = (const int*)  d_in[1];
    const float* W1      = (const float*)d_in[3];
    const float* b1      = (const float*)d_in[4];
    const float* W2      = (const float*)d_in[5];
    const float* b2      = (const float*)d_in[6];
    const float* W3      = (const float*)d_in[7];
    const float* b3      = (const float*)d_in[8];
    float* out = (float*)d_out;

    const int N = in_sizes[1];
    const int S = out_size / 128;

    cudaFuncSetAttribute(mlp_accum_kernel,
                         cudaFuncAttributeMaxDynamicSharedMemorySize, SMEM_A);

    zero_kernel<<<(S * 64 + 255) / 256, 256>>>(S);
    mlp_accum_kernel<<<GRID_A, TPB_A, SMEM_A>>>(f_all, seg_ids, N, W1, b1, W2, b2);
    seg_out_kernel<<<S, 128>>>(W3, b3, out);
}